// round 6
// baseline (speedup 1.0000x reference)
#include <cuda_runtime.h>
#include <math_constants.h>

// Scratch + sync state (no dynamic allocation allowed).
__device__ float g_P4[2 * 256];          // maxpool16(x4)  [b, hw]
__device__ float g_T3[2 * 256 * 256];    // maxpool8(x3)   [b, j, hw]
__device__ int   g_done   = 0;           // prologue blocks completed
__device__ int   g_finish = 0;           // all blocks completed (for replay reset)

#define N_PRO   1024                      // prologue blocks (512 x3 + 512 x4)
#define N_MAIN  8192                      // main blocks
#define N_TOTAL (N_PRO + N_MAIN)

// ---------------------------------------------------------------------------
// Single fused kernel, grid = 9216 x 256.
//   bid [0, 512):     T3[b, j, hw] = maxpool8(x3[b,j])   (x3: [2,256,128,128])
//   bid [512, 1024):  P4[b, hw]    = maxpool16(x4[b,0])  (x4: [2,1,256,256])
//     both release-signal g_done.
//   bid [1024, 9216): main block (b, k): pool x2/x1 into registers (overlaps
//     with prologue HBM traffic), then ONLY THREAD 0 spins on g_done==N_PRO
//     (rest park at __syncthreads), then combine with T3/P4 and stream ff/out.
// Prologue bids < wave-1 capacity and dispatch first -> deadlock-free.
// Last block of the grid resets counters so graph replays start clean.
// ---------------------------------------------------------------------------
__global__ void __launch_bounds__(256) fused_all_kernel(
        const float* __restrict__ x1, const float* __restrict__ x2,
        const float* __restrict__ x3, const float* __restrict__ x4,
        const float* __restrict__ ff, float* __restrict__ out) {
    const int bid = blockIdx.x;
    const int t   = threadIdx.x;

    if (bid < N_PRO) {
        if (bid < 512) {
            // ---- maxpool8 of one full x3 plane ----
            const int b  = bid >> 8, j = bid & 255;
            const int oh = t >> 4, ow = t & 15;
            const float* base = x3 + ((size_t)b * 256 + j) * 16384;
            float m = -CUDART_INF_F;
#pragma unroll
            for (int r = 0; r < 8; ++r) {
                const float4* row = (const float4*)(base + (8 * oh + r) * 128 + 8 * ow);
                float4 v0 = row[0];
                float4 v1 = row[1];
                m = fmaxf(m, fmaxf(fmaxf(v0.x, v0.y), fmaxf(v0.z, v0.w)));
                m = fmaxf(m, fmaxf(fmaxf(v1.x, v1.y), fmaxf(v1.z, v1.w)));
            }
            g_T3[((size_t)b * 256 + j) * 256 + t] = m;
        } else {
            // ---- maxpool16 of x4: one output value per block, tree reduce ----
            const int o  = bid - 512;          // [0, 512)
            const int b  = o >> 8;
            const int p  = o & 255;
            const int oh = p >> 4, ow = p & 15;
            const float* base = x4 + (size_t)b * 65536;
            float v = base[(16 * oh + (t >> 4)) * 256 + 16 * ow + (t & 15)];

            __shared__ float red[8];
#pragma unroll
            for (int s = 16; s > 0; s >>= 1)
                v = fmaxf(v, __shfl_down_sync(0xFFFFFFFFu, v, s));
            if ((t & 31) == 0) red[t >> 5] = v;
            __syncthreads();
            if (t == 0) {
                float m = red[0];
#pragma unroll
                for (int w = 1; w < 8; ++w) m = fmaxf(m, red[w]);
                g_P4[b * 256 + p] = m;
            }
        }
        // Release: this block's T3/P4 writes become visible, then count.
        __syncthreads();
        if (t == 0) {
            __threadfence();
            atomicAdd(&g_done, 1);
        }
    } else {
        // ================= main block =================
        const int B  = bid - N_PRO;            // [0, 8192)
        const int b  = B >> 12, k = B & 4095;
        const int oh = t >> 4, ow = t & 15;

        // ---- prologue-independent HBM reads (overlap with prologue) ----
        const float* x2p = x2 + ((size_t)b * 4096 + k) * 4096;
        float p2 = -CUDART_INF_F;
#pragma unroll
        for (int r = 0; r < 4; ++r) {
            float4 v = *(const float4*)(x2p + (4 * oh + r) * 64 + 4 * ow);
            p2 = fmaxf(p2, fmaxf(fmaxf(v.x, v.y), fmaxf(v.z, v.w)));
        }

        float p1v[4];
#pragma unroll
        for (int m = 0; m < 4; ++m) {
            const int c = k + 4096 * m;
            const float* x1p = x1 + ((size_t)b * 16384 + c) * 1024;
            float2 a0 = *(const float2*)(x1p + (2 * oh)     * 32 + 2 * ow);
            float2 a1 = *(const float2*)(x1p + (2 * oh + 1) * 32 + 2 * ow);
            p1v[m] = fmaxf(fmaxf(a0.x, a0.y), fmaxf(a1.x, a1.y));
        }

        // ---- wait for prologue: ONLY t==0 polls (no L2 spin-storm) ----
        if (t == 0) {
            if (*(volatile int*)&g_done < N_PRO) {
                while (*(volatile int*)&g_done < N_PRO) __nanosleep(512);
            }
            __threadfence();                   // acquire side (fence-to-fence)
        }
        __syncthreads();                       // block-wide release of the wait

        const float basev = p2
                          + g_T3[((size_t)b * 256 + (k & 255)) * 256 + t]
                          + g_P4[b * 256 + t];

#pragma unroll
        for (int m = 0; m < 4; ++m) {
            const int c = k + 4096 * m;
            const float s = basev + p1v[m];
            const size_t o0 = ((size_t)b * 32768 + c) * 256 + t;
            const size_t o1 = o0 + (size_t)16384 * 256;
            out[o0] = fmaxf(s + ff[o0], 0.0f);
            out[o1] = fmaxf(s + ff[o1], 0.0f);
        }
    }

    // ---- replay-safe counter reset: last block of the grid cleans up ----
    __syncthreads();
    if (t == 0) {
        const int old = atomicAdd(&g_finish, 1);
        if (old == N_TOTAL - 1) {
            g_done   = 0;
            g_finish = 0;
            __threadfence();
        }
    }
}

// ---------------------------------------------------------------------------
// Launch: inputs in metadata order: x1, x2, x3, x4, pure_ff
// ---------------------------------------------------------------------------
extern "C" void kernel_launch(void* const* d_in, const int* in_sizes, int n_in,
                              void* d_out, int out_size) {
    const float* x1 = (const float*)d_in[0];
    const float* x2 = (const float*)d_in[1];
    const float* x3 = (const float*)d_in[2];
    const float* x4 = (const float*)d_in[3];
    const float* ff = (const float*)d_in[4];
    float* out = (float*)d_out;

    fused_all_kernel<<<N_TOTAL, 256>>>(x1, x2, x3, x4, ff, out);
}